// round 2
// baseline (speedup 1.0000x reference)
#include <cuda_runtime.h>
#include <math.h>

// Problem constants
#define B_   16
#define S_   64
#define N_   100
#define H_   256
#define BN_  1600
#define NBLK 148     // grid size (<= SM count, avoids wave quantization)
#define MBR  11      // max sequences per block: NBLK*MBR >= BN_

// ---------------------------------------------------------------------------
// Repacked weights (device globals; filled by prep_kernel every launch).
// g_W0/g_W1: [512 k][256 unit] float4 (gates i,f,g,o packed). k<256 -> W_ih,
// k>=256 -> W_hh. Combined biases per unit as float4.
// g_HW: [256 k][512 u] packed head layer-1 (cen 0..127, svd 128..255, lsvd 256..511)
// ---------------------------------------------------------------------------
__device__ float4 g_W0[512 * 256];
__device__ float4 g_W1[512 * 256];
__device__ float4 g_B0[256];
__device__ float4 g_B1[256];
__device__ float  g_HW[256 * 512];
__device__ float  g_HB[512];

__global__ void prep_kernel(
    const float* __restrict__ Wih0, const float* __restrict__ Whh0,
    const float* __restrict__ bih0, const float* __restrict__ bhh0,
    const float* __restrict__ Wih1, const float* __restrict__ Whh1,
    const float* __restrict__ bih1, const float* __restrict__ bhh1,
    const float* __restrict__ cw1,  const float* __restrict__ cb1,
    const float* __restrict__ sw1,  const float* __restrict__ sb1,
    const float* __restrict__ lw1,  const float* __restrict__ lb1)
{
    int idx = blockIdx.x * blockDim.x + threadIdx.x;
    int stride = gridDim.x * blockDim.x;

    // LSTM weights: transpose + gate-interleave
    for (int i = idx; i < 512 * 256; i += stride) {
        int k = i >> 8, j = i & 255;
        int kk = k & 255;
        const float* s0 = (k < 256) ? Wih0 : Whh0;
        const float* s1 = (k < 256) ? Wih1 : Whh1;
        float4 v0, v1;
        v0.x = s0[(0 * 256 + j) * 256 + kk];
        v0.y = s0[(1 * 256 + j) * 256 + kk];
        v0.z = s0[(2 * 256 + j) * 256 + kk];
        v0.w = s0[(3 * 256 + j) * 256 + kk];
        v1.x = s1[(0 * 256 + j) * 256 + kk];
        v1.y = s1[(1 * 256 + j) * 256 + kk];
        v1.z = s1[(2 * 256 + j) * 256 + kk];
        v1.w = s1[(3 * 256 + j) * 256 + kk];
        g_W0[i] = v0;
        g_W1[i] = v1;
    }

    // Head layer-1 packed transpose
    for (int i = idx; i < 256 * 512; i += stride) {
        int k = i >> 9, u = i & 511;
        float v;
        if (u < 128)      v = cw1[u * 256 + k];
        else if (u < 256) v = sw1[(u - 128) * 256 + k];
        else              v = lw1[(u - 256) * 256 + k];
        g_HW[i] = v;
    }

    if (idx < 256) {
        float4 b0, b1;
        b0.x = bih0[idx]       + bhh0[idx];
        b0.y = bih0[256 + idx] + bhh0[256 + idx];
        b0.z = bih0[512 + idx] + bhh0[512 + idx];
        b0.w = bih0[768 + idx] + bhh0[768 + idx];
        b1.x = bih1[idx]       + bhh1[idx];
        b1.y = bih1[256 + idx] + bhh1[256 + idx];
        b1.z = bih1[512 + idx] + bhh1[512 + idx];
        b1.w = bih1[768 + idx] + bhh1[768 + idx];
        g_B0[idx] = b0;
        g_B1[idx] = b1;
    }
    if (idx < 512) {
        g_HB[idx] = (idx < 128) ? cb1[idx]
                  : (idx < 256) ? sb1[idx - 128]
                                : lb1[idx - 256];
    }
}

// ---------------------------------------------------------------------------
// Main fused kernel
// ---------------------------------------------------------------------------
__device__ __forceinline__ float sigf(float x) { return 1.f / (1.f + expf(-x)); }

// One LSTM cell for MBR rows. A: input vecs [MBR][256] (smem). Hs: h state
// [MBR][256] (smem, read then overwritten). C: per-thread cell state (regs).
// Thread tid owns hidden unit tid (all 4 gates).
__device__ __forceinline__ void lstm_cell(
    const float4* __restrict__ W, const float4* __restrict__ Bv,
    const float* __restrict__ A, float* __restrict__ Hs, float* C, int tid)
{
    float4 b = Bv[tid];
    float ai[MBR], af[MBR], ag[MBR], ao[MBR];
#pragma unroll
    for (int r = 0; r < MBR; r++) { ai[r] = b.x; af[r] = b.y; ag[r] = b.z; ao[r] = b.w; }

    const float4* A4 = (const float4*)A;
    const float4* H4 = (const float4*)Hs;
    const float4* Wa = W + tid;              // k < 256 (input part)
    const float4* Wb = W + 256 * 256 + tid;  // k >= 256 (hidden part)

    for (int kk = 0; kk < 64; kk++) {
        float4 wa0 = Wa[(4 * kk + 0) * 256];
        float4 wa1 = Wa[(4 * kk + 1) * 256];
        float4 wa2 = Wa[(4 * kk + 2) * 256];
        float4 wa3 = Wa[(4 * kk + 3) * 256];
        float4 wb0 = Wb[(4 * kk + 0) * 256];
        float4 wb1 = Wb[(4 * kk + 1) * 256];
        float4 wb2 = Wb[(4 * kk + 2) * 256];
        float4 wb3 = Wb[(4 * kk + 3) * 256];
#pragma unroll
        for (int r = 0; r < MBR; r++) {
            float4 av = A4[r * 64 + kk];
            float4 hv = H4[r * 64 + kk];
            ai[r] += wa0.x * av.x + wa1.x * av.y + wa2.x * av.z + wa3.x * av.w
                   + wb0.x * hv.x + wb1.x * hv.y + wb2.x * hv.z + wb3.x * hv.w;
            af[r] += wa0.y * av.x + wa1.y * av.y + wa2.y * av.z + wa3.y * av.w
                   + wb0.y * hv.x + wb1.y * hv.y + wb2.y * hv.z + wb3.y * hv.w;
            ag[r] += wa0.z * av.x + wa1.z * av.y + wa2.z * av.z + wa3.z * av.w
                   + wb0.z * hv.x + wb1.z * hv.y + wb2.z * hv.z + wb3.z * hv.w;
            ao[r] += wa0.w * av.x + wa1.w * av.y + wa2.w * av.z + wa3.w * av.w
                   + wb0.w * hv.x + wb1.w * hv.y + wb2.w * hv.z + wb3.w * hv.w;
        }
    }
    __syncthreads();  // all reads of Hs done before overwrite
#pragma unroll
    for (int r = 0; r < MBR; r++) {
        float iv = sigf(ai[r]);
        float fv = sigf(af[r]);
        float gv = tanhf(ag[r]);
        float ov = sigf(ao[r]);
        float c = fv * C[r] + iv * gv;
        C[r] = c;
        Hs[r * 256 + tid] = ov * tanhf(c);
    }
    __syncthreads();
}

// LayerNorm of Hs rows into OV. Warp w handles rows w, w+8.
__device__ __forceinline__ void layer_norm(
    const float* __restrict__ Hs, float* __restrict__ OV,
    const float* __restrict__ LNG, const float* __restrict__ LNB, int tid)
{
    int w = tid >> 5, lane = tid & 31;
    for (int r = w; r < MBR; r += 8) {
        float v[8];
        float s = 0.f, sq = 0.f;
#pragma unroll
        for (int q = 0; q < 8; q++) {
            v[q] = Hs[r * 256 + lane + 32 * q];
            s += v[q];
            sq += v[q] * v[q];
        }
#pragma unroll
        for (int off = 16; off > 0; off >>= 1) {
            s  += __shfl_xor_sync(0xffffffffu, s, off);
            sq += __shfl_xor_sync(0xffffffffu, sq, off);
        }
        float m = s * (1.f / 256.f);
        float var = sq * (1.f / 256.f) - m * m;
        float inv = rsqrtf(var + 1e-5f);
#pragma unroll
        for (int q = 0; q < 8; q++) {
            int i = lane + 32 * q;
            OV[r * 256 + i] = (v[q] - m) * inv * LNG[i] + LNB[i];
        }
    }
    __syncthreads();
}

__global__ void __launch_bounds__(256, 1) lstm_main(
    const float* __restrict__ x,
    const float* __restrict__ ln_g, const float* __restrict__ ln_b,
    const float* __restrict__ cw2,  const float* __restrict__ cb2,
    const float* __restrict__ sw2,  const float* __restrict__ sb2,
    const float* __restrict__ lw2,  const float* __restrict__ lb2,
    float* __restrict__ out, int steps)
{
    extern __shared__ float sm[];
    float* IV  = sm;                 // [MBR][256] input vector (x_t or ln(h1))
    float* H0  = IV + MBR * 256;     // [MBR][256] layer-0 h
    float* H1  = H0 + MBR * 256;     // [MBR][256] layer-1 h
    float* HID = H1 + MBR * 256;     // [MBR][512] head hidden
    float* LNG = HID + MBR * 512;    // [256]
    float* LNB = LNG + 256;          // [256]

    int tid = threadIdx.x, bid = blockIdx.x;

    float C0[MBR], C1[MBR];
#pragma unroll
    for (int r = 0; r < MBR; r++) {
        C0[r] = 0.f; C1[r] = 0.f;
        H0[r * 256 + tid] = 0.f;
        H1[r * 256 + tid] = 0.f;
    }
    LNG[tid] = ln_g[tid];
    LNB[tid] = ln_b[tid];
    __syncthreads();

    // -------- encoder --------
    for (int t = 0; t < S_; t++) {
#pragma unroll
        for (int r = 0; r < MBR; r++) {
            int s = bid + NBLK * r;
            float v = 0.f;
            if (s < BN_) {
                int b = s / N_, n = s % N_;
                v = x[(b * (S_ * N_) + t * N_ + n) * H_ + tid];
            }
            IV[r * 256 + tid] = v;
        }
        __syncthreads();
        lstm_cell(g_W0, g_B0, IV, H0, C0, tid);
        lstm_cell(g_W1, g_B1, H0, H1, C1, tid);
    }
    layer_norm(H1, IV, LNG, LNB, tid);

    // -------- decoder --------
    for (int td = 0; td < steps; td++) {
        // heads layer 1: thread owns hidden units tid and tid+256
        float a0[MBR], a1[MBR];
        float hb0 = g_HB[tid], hb1v = g_HB[tid + 256];
#pragma unroll
        for (int r = 0; r < MBR; r++) { a0[r] = hb0; a1[r] = hb1v; }
        const float4* IV4 = (const float4*)IV;
        for (int kk = 0; kk < 64; kk++) {
            float w00 = g_HW[(4 * kk + 0) * 512 + tid];
            float w01 = g_HW[(4 * kk + 1) * 512 + tid];
            float w02 = g_HW[(4 * kk + 2) * 512 + tid];
            float w03 = g_HW[(4 * kk + 3) * 512 + tid];
            float w10 = g_HW[(4 * kk + 0) * 512 + tid + 256];
            float w11 = g_HW[(4 * kk + 1) * 512 + tid + 256];
            float w12 = g_HW[(4 * kk + 2) * 512 + tid + 256];
            float w13 = g_HW[(4 * kk + 3) * 512 + tid + 256];
#pragma unroll
            for (int r = 0; r < MBR; r++) {
                float4 av = IV4[r * 64 + kk];
                a0[r] += w00 * av.x + w01 * av.y + w02 * av.z + w03 * av.w;
                a1[r] += w10 * av.x + w11 * av.y + w12 * av.z + w13 * av.w;
            }
        }
#pragma unroll
        for (int r = 0; r < MBR; r++) {
            HID[r * 512 + tid]       = fmaxf(a0[r], 0.f);
            HID[r * 512 + tid + 256] = fmaxf(a1[r], 0.f);
        }
        __syncthreads();

        // heads layer 2 + output write: 242 threads, one (row, channel) each
        if (tid < MBR * 22) {
            int r = tid / 22, c = tid % 22;
            int s = bid + NBLK * r;
            if (s < BN_) {
                const float* wrow;
                const float* hb;
                int len;
                float acc;
                if (c < 4)      { wrow = cw2 + c * 128;       hb = HID + r * 512;       len = 128; acc = cb2[c]; }
                else if (c < 6) { wrow = sw2 + (c - 4) * 128; hb = HID + r * 512 + 128; len = 128; acc = sb2[c - 4]; }
                else            { wrow = lw2 + (c - 6) * 256; hb = HID + r * 512 + 256; len = 256; acc = lb2[c - 6]; }
                for (int k = 0; k < len; k++) acc += wrow[k] * hb[k];
                int b = s / N_, n = s % N_;
                out[((b * steps + td) * N_ + n) * 22 + c] = acc;
            }
        }

        lstm_cell(g_W0, g_B0, IV, H0, C0, tid);
        lstm_cell(g_W1, g_B1, H0, H1, C1, tid);
        layer_norm(H1, IV, LNG, LNB, tid);
    }
}

// ---------------------------------------------------------------------------
extern "C" void kernel_launch(void* const* d_in, const int* in_sizes, int n_in,
                              void* d_out, int out_size)
{
    const float* x    = (const float*)d_in[0];
    const float* Wih0 = (const float*)d_in[1];
    const float* Whh0 = (const float*)d_in[2];
    const float* bih0 = (const float*)d_in[3];
    const float* bhh0 = (const float*)d_in[4];
    const float* Wih1 = (const float*)d_in[5];
    const float* Whh1 = (const float*)d_in[6];
    const float* bih1 = (const float*)d_in[7];
    const float* bhh1 = (const float*)d_in[8];
    const float* ln_g = (const float*)d_in[9];
    const float* ln_b = (const float*)d_in[10];
    const float* cw1  = (const float*)d_in[11];
    const float* cb1  = (const float*)d_in[12];
    const float* cw2  = (const float*)d_in[13];
    const float* cb2  = (const float*)d_in[14];
    const float* sw1  = (const float*)d_in[15];
    const float* sb1  = (const float*)d_in[16];
    const float* sw2  = (const float*)d_in[17];
    const float* sb2  = (const float*)d_in[18];
    const float* lw1  = (const float*)d_in[19];
    const float* lb1  = (const float*)d_in[20];
    const float* lw2  = (const float*)d_in[21];
    const float* lb2  = (const float*)d_in[22];
    float* out = (float*)d_out;

    int steps = out_size / (B_ * N_ * 22);  // 35200 elems per decoder step

    prep_kernel<<<128, 256>>>(Wih0, Whh0, bih0, bhh0, Wih1, Whh1, bih1, bhh1,
                              cw1, cb1, sw1, sb1, lw1, lb1);

    const int smem_bytes = (3 * MBR * 256 + MBR * 512 + 512) * (int)sizeof(float);  // 58368
    cudaFuncSetAttribute(lstm_main, cudaFuncAttributeMaxDynamicSharedMemorySize, smem_bytes);
    lstm_main<<<NBLK, 256, smem_bytes>>>(x, ln_g, ln_b, cw2, cb2, sw2, sb2,
                                         lw2, lb2, out, steps);
}